// round 10
// baseline (speedup 1.0000x reference)
#include <cuda_runtime.h>
#include <math.h>

// ---------------------------------------------------------------------------
// MultiBoxLoss (SSD loss): matching + smooth-L1 + CE + hard negative mining
// B=64, P=24564, C=21, NOBJ=32 (scratch sized to these maxima)
// ---------------------------------------------------------------------------

#define BMAX   64
#define PMAX   24564
#define CNUM   21
#define NOBJ_  32
#define NBIN   65536

#define K1_TPB 128
#define K1_PPT 4
#define K3_TPB 256

// ------------------------------ scratch ------------------------------------
__device__ float              g_overlap[(size_t)BMAX * PMAX];
__device__ int                g_btidx[(size_t)BMAX * PMAX];
__device__ unsigned           g_key[(size_t)BMAX * PMAX];
__device__ unsigned           g_hist[(size_t)BMAX * NBIN];
__device__ unsigned long long g_bestprior[BMAX * NOBJ_];
__device__ int                g_numpos[BMAX];
__device__ double             g_loss_l;
__device__ double             g_loss_c;
__device__ int                g_H[BMAX];
__device__ int                g_r[BMAX];
__device__ int                g_takeall[BMAX];
__device__ int                g_eqtake[BMAX];
__device__ unsigned           g_T[BMAX];

// ------------------------------ helpers ------------------------------------
__device__ __forceinline__ float warpRedF(float v) {
#pragma unroll
    for (int o = 16; o; o >>= 1) v += __shfl_xor_sync(0xffffffffu, v, o);
    return v;
}
__device__ __forceinline__ int warpRedI(int v) {
#pragma unroll
    for (int o = 16; o; o >>= 1) v += __shfl_xor_sync(0xffffffffu, v, o);
    return v;
}

// ------------------------------ kernels ------------------------------------

__global__ void k_init() {
    int i = blockIdx.x * blockDim.x + threadIdx.x;
    if (i < BMAX * NOBJ_) g_bestprior[i] = 0x00000000FFFFFFFFULL; // iou=0, p=0
    if (i < BMAX) {
        g_numpos[i] = 0;
        g_takeall[i] = 0;
        g_eqtake[i] = 0;
        g_T[i] = 0xFFFFFFFFu; // "select none" default
    }
    if (i == 0) { g_loss_l = 0.0; g_loss_c = 0.0; }
}

// Per (b,p): best GT over NOBJ (argmax over n, first-wins).
// Per (b,n): best prior over P via packed u64 atomicMax (smallest p on ties).
__global__ void k_match(const float* __restrict__ priors,
                        const float* __restrict__ tboxes, int P) {
    const int b = blockIdx.y;
    __shared__ float4 sh_t[NOBJ_];
    __shared__ float  sh_ta[NOBJ_];
    __shared__ unsigned long long sh_pack[NOBJ_];
    const int tid = threadIdx.x;
    if (tid < NOBJ_) {
        float4 t = ((const float4*)tboxes)[b * NOBJ_ + tid];
        sh_t[tid] = t;
        sh_ta[tid] = (t.z - t.x) * (t.w - t.y);
        sh_pack[tid] = 0x00000000FFFFFFFFULL;
    }
    __syncthreads();

    const int p0 = blockIdx.x * (K1_TPB * K1_PPT);
    float px0[K1_PPT], py0[K1_PPT], px1[K1_PPT], py1[K1_PPT], pa[K1_PPT];
    int   pp[K1_PPT];
    bool  pv[K1_PPT];
    float bestv[K1_PPT];
    int   bestn[K1_PPT];
#pragma unroll
    for (int k = 0; k < K1_PPT; k++) {
        int p = p0 + tid + k * K1_TPB;
        pp[k] = p; pv[k] = (p < P);
        bestv[k] = 0.f; bestn[k] = 0;
        if (pv[k]) {
            float4 pr = ((const float4*)priors)[p];
            px0[k] = pr.x - pr.z * 0.5f;
            py0[k] = pr.y - pr.w * 0.5f;
            px1[k] = pr.x + pr.z * 0.5f;
            py1[k] = pr.y + pr.w * 0.5f;
            pa[k] = (px1[k] - px0[k]) * (py1[k] - py0[k]);
        }
    }

    for (int n = 0; n < NOBJ_; n++) {
        const float4 t = sh_t[n];
        const float  ta = sh_ta[n];
        float blockmax = __uint_as_float(((const unsigned*)&sh_pack[n])[1]);
#pragma unroll
        for (int k = 0; k < K1_PPT; k++) {
            if (!pv[k]) continue;
            float lx = fmaxf(t.x, px0[k]);
            float ly = fmaxf(t.y, py0[k]);
            float rx = fminf(t.z, px1[k]);
            float ry = fminf(t.w, py1[k]);
            float w = fmaxf(rx - lx, 0.f);
            float h = fmaxf(ry - ly, 0.f);
            float inter = w * h;
            float iou = inter / (ta + pa[k] - inter);
            if (iou > bestv[k]) { bestv[k] = iou; bestn[k] = n; }
            if (iou > blockmax) {
                unsigned long long pk =
                    ((unsigned long long)__float_as_uint(iou) << 32) |
                    (unsigned)(~pp[k]);
                atomicMax(&sh_pack[n], pk);
                blockmax = iou;
            }
        }
    }
#pragma unroll
    for (int k = 0; k < K1_PPT; k++) {
        if (pv[k]) {
            g_overlap[(size_t)b * P + pp[k]] = bestv[k];
            g_btidx[(size_t)b * P + pp[k]]  = bestn[k];
        }
    }
    __syncthreads();
    if (tid < NOBJ_) atomicMax(&g_bestprior[b * NOBJ_ + tid], sh_pack[tid]);
}

// Sequential per-batch scatter (last n wins, matching in-order scatter).
__global__ void k_fixup(int P) {
    int b = threadIdx.x;
#pragma unroll 1
    for (int n = 0; n < NOBJ_; n++) {
        unsigned long long pk = g_bestprior[b * NOBJ_ + n];
        unsigned p = ~(unsigned)pk;
        g_overlap[(size_t)b * P + p] = 2.0f;
        g_btidx[(size_t)b * P + p]  = n;
    }
}

// CE per prior + pos-CE sum + smooth-L1 on positives + num_pos + mining key.
__global__ void k_ce(const float* __restrict__ conf,
                     const float* __restrict__ loc,
                     const float* __restrict__ priors,
                     const float* __restrict__ tboxes,
                     const int*   __restrict__ tlabels, int P) {
    __shared__ float sh[K3_TPB * CNUM];
    const int b = blockIdx.y;
    const int p0 = blockIdx.x * K3_TPB;
    const int np = min(K3_TPB, P - p0);
    const int nf = np * CNUM;
    const float* src = conf + ((size_t)b * P + p0) * CNUM;
    const int tid = threadIdx.x;

    // coalesced staging (float4 when the chunk start is 16B aligned)
    if (((((size_t)b * P + p0) * CNUM) & 3) == 0) {
        const int nf4 = nf >> 2;
        const float4* s4 = (const float4*)src;
        for (int i = tid; i < nf4; i += K3_TPB) ((float4*)sh)[i] = s4[i];
        for (int i = (nf4 << 2) + tid; i < nf; i += K3_TPB) sh[i] = src[i];
    } else {
        for (int i = tid; i < nf; i += K3_TPB) sh[i] = src[i];
    }
    __syncthreads();

    const int p = p0 + tid;
    float l1 = 0.f, posce = 0.f;
    int ispos = 0;
    if (tid < np) {
        const float* x = sh + tid * CNUM;
        float m = x[0];
#pragma unroll
        for (int c = 1; c < CNUM; c++) m = fmaxf(m, x[c]);
        float s = 0.f;
#pragma unroll
        for (int c = 0; c < CNUM; c++) s += __expf(x[c] - m);
        float lse = m + __logf(s);
        float ov = g_overlap[(size_t)b * P + p];
        int   ti = g_btidx[(size_t)b * P + p];
        int  lab = (ov < 0.5f) ? 0 : (tlabels[b * NOBJ_ + ti] + 1);
        float ce = lse - x[lab];
        ispos = (lab > 0);
        g_key[(size_t)b * P + p] = ispos ? 0u : __float_as_uint(fmaxf(ce, 0.f));
        if (ispos) {
            posce = ce;
            float4 t  = ((const float4*)tboxes)[b * NOBJ_ + ti];
            float4 pr = ((const float4*)priors)[p];
            float gx = ((t.x + t.z) * 0.5f - pr.x) / (0.1f * pr.z);
            float gy = ((t.y + t.w) * 0.5f - pr.y) / (0.1f * pr.w);
            float gw = __logf((t.z - t.x) / pr.z) * 5.0f;
            float gh = __logf((t.w - t.y) / pr.w) * 5.0f;
            float4 ld = ((const float4*)loc)[(size_t)b * P + p];
            float d, ad;
            d = ld.x - gx; ad = fabsf(d); l1 += (ad < 1.f) ? 0.5f * d * d : ad - 0.5f;
            d = ld.y - gy; ad = fabsf(d); l1 += (ad < 1.f) ? 0.5f * d * d : ad - 0.5f;
            d = ld.z - gw; ad = fabsf(d); l1 += (ad < 1.f) ? 0.5f * d * d : ad - 0.5f;
            d = ld.w - gh; ad = fabsf(d); l1 += (ad < 1.f) ? 0.5f * d * d : ad - 0.5f;
        }
    }
    float a = warpRedF(l1);
    float bb = warpRedF(posce);
    int   c = warpRedI(ispos);
    __shared__ float sA[K3_TPB / 32], sB[K3_TPB / 32];
    __shared__ int   sC[K3_TPB / 32];
    int w = tid >> 5, l = tid & 31;
    if (l == 0) { sA[w] = a; sB[w] = bb; sC[w] = c; }
    __syncthreads();
    if (w == 0) {
        a = (l < (K3_TPB >> 5)) ? sA[l] : 0.f;
        bb = (l < (K3_TPB >> 5)) ? sB[l] : 0.f;
        c = (l < (K3_TPB >> 5)) ? sC[l] : 0;
        a = warpRedF(a); bb = warpRedF(bb); c = warpRedI(c);
        if (l == 0) {
            if (a != 0.f)  atomicAdd(&g_loss_l, (double)a);
            if (bb != 0.f) atomicAdd(&g_loss_c, (double)bb);
            if (c)         atomicAdd(&g_numpos[b], c);
        }
    }
}

__global__ void k_hist_hi(int P) {
    int b = blockIdx.y;
    int p = blockIdx.x * K3_TPB + threadIdx.x;
    if (p < P) {
        unsigned key = g_key[(size_t)b * P + p];
        if (key) atomicAdd(&g_hist[(size_t)b * NBIN + (key >> 16)], 1u);
    }
}

// one block per batch: 16-bit radix select (hi)
__global__ void k_sel_hi(int Pm1) {
    const int b = blockIdx.x;
    const int np = g_numpos[b];
    int k = 3 * np; if (k > Pm1) k = Pm1;
    const unsigned t = threadIdx.x;
    if (k <= 0) {
        if (t == 0) { g_takeall[b] = 1; g_T[b] = 0xFFFFFFFFu; g_eqtake[b] = 0; }
        return;
    }
    __shared__ unsigned s_cnt[256];
    const unsigned* h = g_hist + (size_t)b * NBIN;
    const unsigned base = NBIN - 256u * (t + 1u);
    unsigned S = 0;
    for (int i = 0; i < 256; i++) S += h[base + i];
    s_cnt[t] = S; __syncthreads();
    for (int off = 1; off < 256; off <<= 1) {
        unsigned v = (t >= (unsigned)off) ? s_cnt[t - off] : 0u;
        __syncthreads();
        s_cnt[t] += v;
        __syncthreads();
    }
    const unsigned incl = s_cnt[t], excl = incl - S, total = s_cnt[255];
    const unsigned uk = (unsigned)k;
    if (total < uk) { // take all negatives
        if (t == 0) { g_takeall[b] = 1; g_T[b] = 0u; g_eqtake[b] = 0; }
        return;
    }
    if (excl < uk && incl >= uk) {
        unsigned c = excl;
        for (int i = 255; i >= 0; i--) {
            unsigned hv = h[base + i];
            if (c + hv >= uk) {
                g_H[b] = (int)(base + i);
                g_r[b] = (int)(uk - c);
                g_takeall[b] = 0;
                break;
            }
            c += hv;
        }
    }
}

__global__ void k_hist_lo(int P) {
    int b = blockIdx.y;
    if (g_takeall[b]) return;
    int p = blockIdx.x * K3_TPB + threadIdx.x;
    if (p < P) {
        unsigned key = g_key[(size_t)b * P + p];
        if (key && (int)(key >> 16) == g_H[b])
            atomicAdd(&g_hist[(size_t)b * NBIN + (key & 0xFFFFu)], 1u);
    }
}

__global__ void k_sel_lo() {
    const int b = blockIdx.x;
    if (g_takeall[b]) return;
    const unsigned r = (unsigned)g_r[b];
    const unsigned t = threadIdx.x;
    __shared__ unsigned s_cnt[256];
    const unsigned* h = g_hist + (size_t)b * NBIN;
    const unsigned base = NBIN - 256u * (t + 1u);
    unsigned S = 0;
    for (int i = 0; i < 256; i++) S += h[base + i];
    s_cnt[t] = S; __syncthreads();
    for (int off = 1; off < 256; off <<= 1) {
        unsigned v = (t >= (unsigned)off) ? s_cnt[t - off] : 0u;
        __syncthreads();
        s_cnt[t] += v;
        __syncthreads();
    }
    const unsigned incl = s_cnt[t], excl = incl - S;
    if (excl < r && incl >= r) {
        unsigned c = excl;
        for (int i = 255; i >= 0; i--) {
            unsigned hv = h[base + i];
            if (c + hv >= r) {
                unsigned L = base + i;
                g_T[b] = ((unsigned)g_H[b] << 16) | L;
                int eq = (int)(r - c);
                g_eqtake[b] = eq > 0 ? eq : 0;
                break;
            }
            c += hv;
        }
    }
}

__global__ void k_negsum(int P) {
    const int b = blockIdx.y;
    const unsigned T = g_T[b];
    int p = blockIdx.x * K3_TPB + threadIdx.x;
    float v = 0.f;
    if (p < P) {
        unsigned key = g_key[(size_t)b * P + p];
        if (key > T) v = __uint_as_float(key);
    }
    float a = warpRedF(v);
    __shared__ float sA[K3_TPB / 32];
    int w = threadIdx.x >> 5, l = threadIdx.x & 31;
    if (l == 0) sA[w] = a;
    __syncthreads();
    if (w == 0) {
        a = (l < (K3_TPB >> 5)) ? sA[l] : 0.f;
        a = warpRedF(a);
        if (l == 0 && a != 0.f) atomicAdd(&g_loss_c, (double)a);
    }
}

__global__ void k_final(float* out, int B) {
    double lc = g_loss_c;
    int n = 0;
    for (int b = 0; b < B; b++) {
        n += g_numpos[b];
        int e = g_eqtake[b];
        if (e > 0) lc += (double)e * (double)__uint_as_float(g_T[b]);
    }
    double N = (n > 0) ? (double)n : 1.0;
    out[0] = (float)(g_loss_l / N);
    out[1] = (float)(lc / N);
}

// ------------------------------ launch -------------------------------------
extern "C" void kernel_launch(void* const* d_in, const int* in_sizes, int n_in,
                              void* d_out, int out_size) {
    const float* loc     = (const float*)d_in[0];
    const float* conf    = (const float*)d_in[1];
    const float* priors  = (const float*)d_in[2];
    const float* tboxes  = (const float*)d_in[3];
    const int*   tlabels = (const int*)d_in[4];

    int P = in_sizes[2] / 4;
    int B = in_sizes[0] / (P * 4);
    if (B > BMAX) B = BMAX;

    k_init<<<8, 256>>>();

    dim3 g1((P + K1_TPB * K1_PPT - 1) / (K1_TPB * K1_PPT), B);
    k_match<<<g1, K1_TPB>>>(priors, tboxes, P);

    k_fixup<<<1, B>>>(P);

    dim3 g3((P + K3_TPB - 1) / K3_TPB, B);
    k_ce<<<g3, K3_TPB>>>(conf, loc, priors, tboxes, tlabels, P);

    void* histPtr = nullptr;
    cudaGetSymbolAddress(&histPtr, g_hist);

    cudaMemsetAsync(histPtr, 0, (size_t)B * NBIN * sizeof(unsigned));
    k_hist_hi<<<g3, K3_TPB>>>(P);
    k_sel_hi<<<B, 256>>>(P - 1);

    cudaMemsetAsync(histPtr, 0, (size_t)B * NBIN * sizeof(unsigned));
    k_hist_lo<<<g3, K3_TPB>>>(P);
    k_sel_lo<<<B, 256>>>();

    k_negsum<<<g3, K3_TPB>>>(P);
    k_final<<<1, 1>>>((float*)d_out, B);
}

// round 11
// speedup vs baseline: 2.2017x; 2.2017x over previous
#include <cuda_runtime.h>
#include <math.h>

// ---------------------------------------------------------------------------
// MultiBoxLoss (SSD loss): matching + smooth-L1 + CE + hard negative mining
// B=64, P=24564, C=21, NOBJ=32 (scratch sized to these maxima)
// ---------------------------------------------------------------------------

#define BMAX   64
#define PMAX   24564
#define CNUM   21
#define NOBJ_  32

#define K1_TPB 128
#define K1_PPT 4

#define K3_TPB   256
#define TILE_P   256
#define TILES_PB 4

// ------------------------------ scratch ------------------------------------
__device__ unsigned           g_match[(size_t)BMAX * PMAX];  // (n<<1)|pos
__device__ unsigned           g_key[(size_t)BMAX * PMAX];    // CE bits (0 = pos)
__device__ unsigned long long g_bestprior[BMAX * NOBJ_];
__device__ int                g_numpos[BMAX];
__device__ double             g_loss_l;
__device__ double             g_loss_c;

// ------------------------------ helpers ------------------------------------
__device__ __forceinline__ float warpRedF(float v) {
#pragma unroll
    for (int o = 16; o; o >>= 1) v += __shfl_xor_sync(0xffffffffu, v, o);
    return v;
}
__device__ __forceinline__ int warpRedI(int v) {
#pragma unroll
    for (int o = 16; o; o >>= 1) v += __shfl_xor_sync(0xffffffffu, v, o);
    return v;
}
__device__ __forceinline__ void cp_async16(unsigned s, const float* g) {
    asm volatile("cp.async.cg.shared.global [%0], [%1], 16;\n" :: "r"(s), "l"(g));
}
__device__ __forceinline__ void cp_async4(unsigned s, const float* g) {
    asm volatile("cp.async.ca.shared.global [%0], [%1], 4;\n" :: "r"(s), "l"(g));
}
__device__ __forceinline__ void cp_commit() {
    asm volatile("cp.async.commit_group;\n");
}
template <int N>
__device__ __forceinline__ void cp_wait() {
    asm volatile("cp.async.wait_group %0;\n" :: "n"(N));
}

// ------------------------------ kernels ------------------------------------

__global__ void k_init() {
    int i = blockIdx.x * blockDim.x + threadIdx.x;
    if (i < BMAX * NOBJ_) g_bestprior[i] = 0x00000000FFFFFFFFULL; // iou=0, p=0
    if (i < BMAX) g_numpos[i] = 0;
    if (i == 0) { g_loss_l = 0.0; g_loss_c = 0.0; }
}

// Per (b,p): best GT over NOBJ (argmax over n, first-wins, division-free).
// Per (b,n): best prior over P via packed u64 atomicMax (smallest p on ties).
__global__ void k_match(const float* __restrict__ priors,
                        const float* __restrict__ tboxes, int P) {
    const int b = blockIdx.y;
    __shared__ float4 sh_t[NOBJ_];
    __shared__ float  sh_ta[NOBJ_];
    __shared__ unsigned long long sh_pack[NOBJ_];
    const int tid = threadIdx.x;
    if (tid < NOBJ_) {
        float4 t = ((const float4*)tboxes)[b * NOBJ_ + tid];
        sh_t[tid] = t;
        sh_ta[tid] = (t.z - t.x) * (t.w - t.y);
        sh_pack[tid] = 0x00000000FFFFFFFFULL;
    }
    __syncthreads();

    const int p0 = blockIdx.x * (K1_TPB * K1_PPT);
    float px0[K1_PPT], py0[K1_PPT], px1[K1_PPT], py1[K1_PPT], pa[K1_PPT];
    int   pp[K1_PPT];
    bool  pv[K1_PPT];
    float bi[K1_PPT], bu[K1_PPT];   // best inter / best union (ratio compare)
    int   bn[K1_PPT];
#pragma unroll
    for (int k = 0; k < K1_PPT; k++) {
        int p = p0 + tid + k * K1_TPB;
        pp[k] = p; pv[k] = (p < P);
        bi[k] = 0.f; bu[k] = 1.f; bn[k] = 0;
        if (pv[k]) {
            float4 pr = ((const float4*)priors)[p];
            px0[k] = pr.x - pr.z * 0.5f;
            py0[k] = pr.y - pr.w * 0.5f;
            px1[k] = pr.x + pr.z * 0.5f;
            py1[k] = pr.y + pr.w * 0.5f;
            pa[k] = (px1[k] - px0[k]) * (py1[k] - py0[k]);
        }
    }

    for (int n = 0; n < NOBJ_; n++) {
        const float4 t = sh_t[n];
        const float  ta = sh_ta[n];
        float bm = __uint_as_float(((const unsigned*)&sh_pack[n])[1]);
#pragma unroll
        for (int k = 0; k < K1_PPT; k++) {
            if (!pv[k]) continue;
            float lx = fmaxf(t.x, px0[k]);
            float ly = fmaxf(t.y, py0[k]);
            float rx = fminf(t.z, px1[k]);
            float ry = fminf(t.w, py1[k]);
            float w = fmaxf(rx - lx, 0.f);
            float h = fmaxf(ry - ly, 0.f);
            float inter = w * h;
            float uni = ta + pa[k] - inter;
            // per-prior argmax over n: inter/uni > bi/bu  <=>  inter*bu > bi*uni
            if (inter * bu[k] > bi[k] * uni) {
                bi[k] = inter; bu[k] = uni; bn[k] = n;
            }
            // per-GT argmax over p: only divide in the rare "exceeds block max" case
            if (inter > bm * uni) {
                float iou = inter / uni;
                if (iou > bm) {
                    unsigned long long pk =
                        ((unsigned long long)__float_as_uint(iou) << 32) |
                        (unsigned)(~pp[k]);
                    atomicMax(&sh_pack[n], pk);
                    bm = iou;
                }
            }
        }
    }
#pragma unroll
    for (int k = 0; k < K1_PPT; k++) {
        if (pv[k]) {
            unsigned pos = (2.0f * bi[k] >= bu[k]) ? 1u : 0u;  // iou >= 0.5
            g_match[(size_t)b * P + pp[k]] = ((unsigned)bn[k] << 1) | pos;
        }
    }
    __syncthreads();
    if (tid < NOBJ_) atomicMax(&g_bestprior[b * NOBJ_ + tid], sh_pack[tid]);
}

// Per-batch scatter (per-thread store order preserves last-n-wins on dup p).
__global__ void k_fixup(int P, int B) {
    int b = threadIdx.x;
    if (b >= B) return;
#pragma unroll
    for (int n = 0; n < NOBJ_; n++) {
        unsigned long long pk = g_bestprior[b * NOBJ_ + n];
        unsigned p = ~(unsigned)pk;
        g_match[(size_t)b * P + p] = ((unsigned)n << 1) | 1u;
    }
}

// CE per prior + pos-CE sum + smooth-L1 on positives + num_pos + mining key.
// cp.async double-buffered, TILES_PB tiles per block.
__global__ void __launch_bounds__(K3_TPB)
k_ce(const float* __restrict__ conf,
     const float* __restrict__ loc,
     const float* __restrict__ priors,
     const float* __restrict__ tboxes,
     const int*   __restrict__ tlabels, int P, int NT) {
    __shared__ float sh[2][TILE_P * CNUM];
    const int b = blockIdx.y;
    const int tid = threadIdx.x;
    const int tile0 = blockIdx.x * TILES_PB;
    const int ntiles = min(TILES_PB, NT - tile0);
    if (ntiles <= 0) return;

    // stage tile into buffer via cp.async
    auto stage = [&](int buf, int tile) {
        int p0 = tile * TILE_P;
        int np = min(TILE_P, P - p0);
        int nf = np * CNUM;
        const float* src = conf + ((size_t)b * P + p0) * CNUM;
        unsigned sbase = (unsigned)__cvta_generic_to_shared(&sh[buf][0]);
        if ((((size_t)src) & 15) == 0 && (nf & 3) == 0) {
            int nf4 = nf >> 2;
            for (int i = tid; i < nf4; i += K3_TPB)
                cp_async16(sbase + i * 16, src + i * 4);
        } else {
            for (int i = tid; i < nf; i += K3_TPB)
                cp_async4(sbase + i * 4, src + i);
        }
    };

    stage(0, tile0);
    cp_commit();

    float l1 = 0.f, posce = 0.f;
    int npos = 0;

    for (int t = 0; t < ntiles; t++) {
        if (t + 1 < ntiles) {
            stage((t + 1) & 1, tile0 + t + 1);
            cp_commit();
            cp_wait<1>();
        } else {
            cp_wait<0>();
        }
        __syncthreads();

        const int p0 = (tile0 + t) * TILE_P;
        const int np = min(TILE_P, P - p0);
        if (tid < np) {
            const float* x = &sh[t & 1][tid * CNUM];
            float m = x[0];
#pragma unroll
            for (int c = 1; c < CNUM; c++) m = fmaxf(m, x[c]);
            float s = 0.f;
#pragma unroll
            for (int c = 0; c < CNUM; c++) s += __expf(x[c] - m);
            float lse = m + __logf(s);

            const int p = p0 + tid;
            unsigned mm = g_match[(size_t)b * P + p];
            int ispos = (int)(mm & 1u);
            int ti = (int)(mm >> 1);
            int lab = ispos ? (tlabels[b * NOBJ_ + ti] + 1) : 0;
            float ce = lse - x[lab];
            g_key[(size_t)b * P + p] = ispos ? 0u : __float_as_uint(fmaxf(ce, 0.f));
            if (ispos) {
                posce += ce;
                npos++;
                float4 tb = ((const float4*)tboxes)[b * NOBJ_ + ti];
                float4 pr = ((const float4*)priors)[p];
                float gx = ((tb.x + tb.z) * 0.5f - pr.x) / (0.1f * pr.z);
                float gy = ((tb.y + tb.w) * 0.5f - pr.y) / (0.1f * pr.w);
                float gw = __logf((tb.z - tb.x) / pr.z) * 5.0f;
                float gh = __logf((tb.w - tb.y) / pr.w) * 5.0f;
                float4 ld = ((const float4*)loc)[(size_t)b * P + p];
                float d, ad;
                d = ld.x - gx; ad = fabsf(d); l1 += (ad < 1.f) ? 0.5f * d * d : ad - 0.5f;
                d = ld.y - gy; ad = fabsf(d); l1 += (ad < 1.f) ? 0.5f * d * d : ad - 0.5f;
                d = ld.z - gw; ad = fabsf(d); l1 += (ad < 1.f) ? 0.5f * d * d : ad - 0.5f;
                d = ld.w - gh; ad = fabsf(d); l1 += (ad < 1.f) ? 0.5f * d * d : ad - 0.5f;
            }
        }
        __syncthreads();   // buffer (t&1) may be re-staged next iteration
    }

    float a = warpRedF(l1);
    float bb = warpRedF(posce);
    int   c = warpRedI(npos);
    __shared__ float sA[K3_TPB / 32], sB[K3_TPB / 32];
    __shared__ int   sC[K3_TPB / 32];
    int w = tid >> 5, l = tid & 31;
    if (l == 0) { sA[w] = a; sB[w] = bb; sC[w] = c; }
    __syncthreads();
    if (w == 0) {
        a = (l < (K3_TPB >> 5)) ? sA[l] : 0.f;
        bb = (l < (K3_TPB >> 5)) ? sB[l] : 0.f;
        c = (l < (K3_TPB >> 5)) ? sC[l] : 0;
        a = warpRedF(a); bb = warpRedF(bb); c = warpRedI(c);
        if (l == 0) {
            if (a != 0.f)  atomicAdd(&g_loss_l, (double)a);
            if (bb != 0.f) atomicAdd(&g_loss_c, (double)bb);
            if (c)         atomicAdd(&g_numpos[blockIdx.y], c);
        }
    }
}

// Hard-negative mining: one block per batch. MSB-first 8-bit radix select
// (4 passes over this batch's 98KB key slice; passes 2-4 hit L1), then the
// sum of selected negatives, all fused.
__global__ void __launch_bounds__(1024) k_mine(int P) {
    const int b = blockIdx.x;
    const int tid = threadIdx.x;
    __shared__ unsigned sh_hist[256];
    __shared__ unsigned sh_suf[256];
    __shared__ unsigned sh_pref, sh_mask, sh_k;
    __shared__ int sh_state;   // 0 normal, 1 take-all, 2 none
    const unsigned* __restrict__ keys = g_key + (size_t)b * P;

    if (tid == 0) {
        long long k = 3LL * (long long)g_numpos[b];
        if (k > P - 1) k = P - 1;
        sh_k = (unsigned)(k > 0 ? k : 0);
        sh_pref = 0u; sh_mask = 0u;
        sh_state = (k <= 0) ? 2 : 0;
    }
    __syncthreads();

    if (sh_state == 0) {
        for (int j = 3; j >= 0; j--) {
            if (tid < 256) sh_hist[tid] = 0u;
            __syncthreads();
            const unsigned mask = sh_mask, pref = sh_pref;
            for (int i = tid; i < P; i += 1024) {
                unsigned key = keys[i];
                if (key && (key & mask) == pref)
                    atomicAdd(&sh_hist[(key >> (8 * j)) & 255u], 1u);
            }
            __syncthreads();
            if (tid < 256) sh_suf[tid] = sh_hist[tid];
            __syncthreads();
            // inclusive suffix scan over 256 bins
            for (int off = 1; off < 256; off <<= 1) {
                unsigned v = 0;
                if (tid < 256 && tid + off < 256) v = sh_suf[tid + off];
                __syncthreads();
                if (tid < 256) sh_suf[tid] += v;
                __syncthreads();
            }
            if (tid == 0 && j == 3 && sh_suf[0] < sh_k) sh_state = 1;
            __syncthreads();
            if (sh_state == 1) break;
            if (tid < 256) {
                unsigned incl  = sh_suf[tid];
                unsigned above = (tid == 255) ? 0u : sh_suf[tid + 1];
                unsigned k = sh_k;
                if (above < k && incl >= k) {
                    sh_pref = pref | ((unsigned)tid << (8 * j));
                    sh_mask = mask | (0xFFu << (8 * j));
                    sh_k = k - above;
                }
            }
            __syncthreads();
        }
    }

    const int st = sh_state;
    const unsigned T = sh_pref;
    float acc = 0.f;
    if (st == 1) {
        for (int i = tid; i < P; i += 1024) {
            unsigned key = keys[i];
            if (key) acc += __uint_as_float(key);
        }
    } else if (st == 0) {
        for (int i = tid; i < P; i += 1024) {
            unsigned key = keys[i];
            if (key > T) acc += __uint_as_float(key);
        }
    }
    acc = warpRedF(acc);
    __shared__ float sA[32];
    int w = tid >> 5, l = tid & 31;
    if (l == 0) sA[w] = acc;
    __syncthreads();
    if (w == 0) {
        acc = sA[l];
        acc = warpRedF(acc);
        if (l == 0) {
            double tot = (double)acc;
            if (st == 0) tot += (double)sh_k * (double)__uint_as_float(T);
            if (tot != 0.0) atomicAdd(&g_loss_c, tot);
        }
    }
}

__global__ void k_final(float* out, int B) {
    int l = threadIdx.x;                       // 32 threads
    int n = 0;
    for (int b = l; b < B; b += 32) n += g_numpos[b];
    n = warpRedI(n);
    if (l == 0) {
        double N = (n > 0) ? (double)n : 1.0;
        out[0] = (float)(g_loss_l / N);
        out[1] = (float)(g_loss_c / N);
    }
}

// ------------------------------ launch -------------------------------------
extern "C" void kernel_launch(void* const* d_in, const int* in_sizes, int n_in,
                              void* d_out, int out_size) {
    const float* loc     = (const float*)d_in[0];
    const float* conf    = (const float*)d_in[1];
    const float* priors  = (const float*)d_in[2];
    const float* tboxes  = (const float*)d_in[3];
    const int*   tlabels = (const int*)d_in[4];

    int P = in_sizes[2] / 4;
    int B = in_sizes[0] / (P * 4);
    if (B > BMAX) B = BMAX;

    k_init<<<8, 256>>>();

    dim3 g1((P + K1_TPB * K1_PPT - 1) / (K1_TPB * K1_PPT), B);
    k_match<<<g1, K1_TPB>>>(priors, tboxes, P);

    k_fixup<<<1, BMAX>>>(P, B);

    int NT = (P + TILE_P - 1) / TILE_P;
    dim3 g3((NT + TILES_PB - 1) / TILES_PB, B);
    k_ce<<<g3, K3_TPB>>>(conf, loc, priors, tboxes, tlabels, P, NT);

    k_mine<<<B, 1024>>>(P);

    k_final<<<1, 32>>>((float*)d_out, B);
}

// round 12
// speedup vs baseline: 2.2026x; 1.0004x over previous
#include <cuda_runtime.h>
#include <math.h>

// ---------------------------------------------------------------------------
// MultiBoxLoss (SSD loss): matching + smooth-L1 + CE + hard negative mining
// B=64, P=24564, C=21, NOBJ=32 (scratch sized to these maxima)
// ---------------------------------------------------------------------------

#define BMAX   64
#define PMAX   24564
#define CNUM   21
#define NOBJ_  32

#define K1_TPB 128
#define K1_PPT 4

#define K3_TPB   256
#define TILE_P   256
#define TILES_PB 4

// ------------------------------ scratch ------------------------------------
__device__ unsigned           g_match[(size_t)BMAX * PMAX];  // (n<<1)|pos
__device__ unsigned           g_key[(size_t)BMAX * PMAX];    // CE bits (0 = pos)
__device__ unsigned long long g_bestprior[BMAX * NOBJ_];
__device__ int                g_numpos[BMAX];
__device__ double             g_loss_l;
__device__ double             g_loss_c;

// ------------------------------ helpers ------------------------------------
__device__ __forceinline__ float warpRedF(float v) {
#pragma unroll
    for (int o = 16; o; o >>= 1) v += __shfl_xor_sync(0xffffffffu, v, o);
    return v;
}
__device__ __forceinline__ int warpRedI(int v) {
#pragma unroll
    for (int o = 16; o; o >>= 1) v += __shfl_xor_sync(0xffffffffu, v, o);
    return v;
}
__device__ __forceinline__ void cp_async16(unsigned s, const float* g) {
    asm volatile("cp.async.cg.shared.global [%0], [%1], 16;\n" :: "r"(s), "l"(g));
}
__device__ __forceinline__ void cp_async4(unsigned s, const float* g) {
    asm volatile("cp.async.ca.shared.global [%0], [%1], 4;\n" :: "r"(s), "l"(g));
}
__device__ __forceinline__ void cp_commit() {
    asm volatile("cp.async.commit_group;\n");
}
template <int N>
__device__ __forceinline__ void cp_wait() {
    asm volatile("cp.async.wait_group %0;\n" :: "n"(N));
}

// ------------------------------ kernels ------------------------------------

__global__ void k_init() {
    int i = blockIdx.x * blockDim.x + threadIdx.x;
    if (i < BMAX * NOBJ_) g_bestprior[i] = 0x00000000FFFFFFFFULL; // iou=0, p=0
    if (i < BMAX) g_numpos[i] = 0;
    if (i == 0) { g_loss_l = 0.0; g_loss_c = 0.0; }
}

// Per (b,p): best GT over NOBJ (argmax over n, first-wins, division-free).
// Per (b,n): best prior over P via packed u64 atomicMax (smallest p on ties).
__global__ void k_match(const float* __restrict__ priors,
                        const float* __restrict__ tboxes, int P) {
    const int b = blockIdx.y;
    __shared__ float4 sh_t[NOBJ_];
    __shared__ float  sh_ta[NOBJ_];
    __shared__ unsigned long long sh_pack[NOBJ_];
    const int tid = threadIdx.x;
    if (tid < NOBJ_) {
        float4 t = ((const float4*)tboxes)[b * NOBJ_ + tid];
        sh_t[tid] = t;
        sh_ta[tid] = (t.z - t.x) * (t.w - t.y);
        sh_pack[tid] = 0x00000000FFFFFFFFULL;
    }
    __syncthreads();

    const int p0 = blockIdx.x * (K1_TPB * K1_PPT);
    float px0[K1_PPT], py0[K1_PPT], px1[K1_PPT], py1[K1_PPT], pa[K1_PPT];
    int   pp[K1_PPT];
    bool  pv[K1_PPT];
    float bi[K1_PPT], bu[K1_PPT];   // best inter / best union (ratio compare)
    int   bn[K1_PPT];
#pragma unroll
    for (int k = 0; k < K1_PPT; k++) {
        int p = p0 + tid + k * K1_TPB;
        pp[k] = p; pv[k] = (p < P);
        bi[k] = 0.f; bu[k] = 1.f; bn[k] = 0;
        if (pv[k]) {
            float4 pr = ((const float4*)priors)[p];
            px0[k] = pr.x - pr.z * 0.5f;
            py0[k] = pr.y - pr.w * 0.5f;
            px1[k] = pr.x + pr.z * 0.5f;
            py1[k] = pr.y + pr.w * 0.5f;
            pa[k] = (px1[k] - px0[k]) * (py1[k] - py0[k]);
        }
    }

    for (int n = 0; n < NOBJ_; n++) {
        const float4 t = sh_t[n];
        const float  ta = sh_ta[n];
        float bm = __uint_as_float(((const unsigned*)&sh_pack[n])[1]);
#pragma unroll
        for (int k = 0; k < K1_PPT; k++) {
            if (!pv[k]) continue;
            float lx = fmaxf(t.x, px0[k]);
            float ly = fmaxf(t.y, py0[k]);
            float rx = fminf(t.z, px1[k]);
            float ry = fminf(t.w, py1[k]);
            float w = fmaxf(rx - lx, 0.f);
            float h = fmaxf(ry - ly, 0.f);
            float inter = w * h;
            float uni = ta + pa[k] - inter;
            // per-prior argmax over n: inter/uni > bi/bu  <=>  inter*bu > bi*uni
            if (inter * bu[k] > bi[k] * uni) {
                bi[k] = inter; bu[k] = uni; bn[k] = n;
            }
            // per-GT argmax over p: only divide in the rare "exceeds block max" case
            if (inter > bm * uni) {
                float iou = inter / uni;
                if (iou > bm) {
                    unsigned long long pk =
                        ((unsigned long long)__float_as_uint(iou) << 32) |
                        (unsigned)(~pp[k]);
                    atomicMax(&sh_pack[n], pk);
                    bm = iou;
                }
            }
        }
    }
#pragma unroll
    for (int k = 0; k < K1_PPT; k++) {
        if (pv[k]) {
            unsigned pos = (2.0f * bi[k] >= bu[k]) ? 1u : 0u;  // iou >= 0.5
            g_match[(size_t)b * P + pp[k]] = ((unsigned)bn[k] << 1) | pos;
        }
    }
    __syncthreads();
    if (tid < NOBJ_) atomicMax(&g_bestprior[b * NOBJ_ + tid], sh_pack[tid]);
}

// Per-batch scatter (per-thread store order preserves last-n-wins on dup p).
__global__ void k_fixup(int P, int B) {
    int b = threadIdx.x;
    if (b >= B) return;
#pragma unroll
    for (int n = 0; n < NOBJ_; n++) {
        unsigned long long pk = g_bestprior[b * NOBJ_ + n];
        unsigned p = ~(unsigned)pk;
        g_match[(size_t)b * P + p] = ((unsigned)n << 1) | 1u;
    }
}

// CE per prior + pos-CE sum + smooth-L1 on positives + num_pos + mining key.
// cp.async double-buffered, TILES_PB tiles per block.
__global__ void __launch_bounds__(K3_TPB)
k_ce(const float* __restrict__ conf,
     const float* __restrict__ loc,
     const float* __restrict__ priors,
     const float* __restrict__ tboxes,
     const int*   __restrict__ tlabels, int P, int NT) {
    __shared__ float sh[2][TILE_P * CNUM];
    const int b = blockIdx.y;
    const int tid = threadIdx.x;
    const int tile0 = blockIdx.x * TILES_PB;
    const int ntiles = min(TILES_PB, NT - tile0);
    if (ntiles <= 0) return;

    // stage tile into buffer via cp.async
    auto stage = [&](int buf, int tile) {
        int p0 = tile * TILE_P;
        int np = min(TILE_P, P - p0);
        int nf = np * CNUM;
        const float* src = conf + ((size_t)b * P + p0) * CNUM;
        unsigned sbase = (unsigned)__cvta_generic_to_shared(&sh[buf][0]);
        if ((((size_t)src) & 15) == 0 && (nf & 3) == 0) {
            int nf4 = nf >> 2;
            for (int i = tid; i < nf4; i += K3_TPB)
                cp_async16(sbase + i * 16, src + i * 4);
        } else {
            for (int i = tid; i < nf; i += K3_TPB)
                cp_async4(sbase + i * 4, src + i);
        }
    };

    stage(0, tile0);
    cp_commit();

    float l1 = 0.f, posce = 0.f;
    int npos = 0;

    for (int t = 0; t < ntiles; t++) {
        if (t + 1 < ntiles) {
            stage((t + 1) & 1, tile0 + t + 1);
            cp_commit();
            cp_wait<1>();
        } else {
            cp_wait<0>();
        }
        __syncthreads();

        const int p0 = (tile0 + t) * TILE_P;
        const int np = min(TILE_P, P - p0);
        if (tid < np) {
            const float* x = &sh[t & 1][tid * CNUM];
            float m = x[0];
#pragma unroll
            for (int c = 1; c < CNUM; c++) m = fmaxf(m, x[c]);
            float s = 0.f;
#pragma unroll
            for (int c = 0; c < CNUM; c++) s += __expf(x[c] - m);
            float lse = m + __logf(s);

            const int p = p0 + tid;
            unsigned mm = g_match[(size_t)b * P + p];
            int ispos = (int)(mm & 1u);
            int ti = (int)(mm >> 1);
            int lab = ispos ? (tlabels[b * NOBJ_ + ti] + 1) : 0;
            float ce = lse - x[lab];
            g_key[(size_t)b * P + p] = ispos ? 0u : __float_as_uint(fmaxf(ce, 0.f));
            if (ispos) {
                posce += ce;
                npos++;
                float4 tb = ((const float4*)tboxes)[b * NOBJ_ + ti];
                float4 pr = ((const float4*)priors)[p];
                float gx = ((tb.x + tb.z) * 0.5f - pr.x) / (0.1f * pr.z);
                float gy = ((tb.y + tb.w) * 0.5f - pr.y) / (0.1f * pr.w);
                float gw = __logf((tb.z - tb.x) / pr.z) * 5.0f;
                float gh = __logf((tb.w - tb.y) / pr.w) * 5.0f;
                float4 ld = ((const float4*)loc)[(size_t)b * P + p];
                float d, ad;
                d = ld.x - gx; ad = fabsf(d); l1 += (ad < 1.f) ? 0.5f * d * d : ad - 0.5f;
                d = ld.y - gy; ad = fabsf(d); l1 += (ad < 1.f) ? 0.5f * d * d : ad - 0.5f;
                d = ld.z - gw; ad = fabsf(d); l1 += (ad < 1.f) ? 0.5f * d * d : ad - 0.5f;
                d = ld.w - gh; ad = fabsf(d); l1 += (ad < 1.f) ? 0.5f * d * d : ad - 0.5f;
            }
        }
        __syncthreads();   // buffer (t&1) may be re-staged next iteration
    }

    float a = warpRedF(l1);
    float bb = warpRedF(posce);
    int   c = warpRedI(npos);
    __shared__ float sA[K3_TPB / 32], sB[K3_TPB / 32];
    __shared__ int   sC[K3_TPB / 32];
    int w = tid >> 5, l = tid & 31;
    if (l == 0) { sA[w] = a; sB[w] = bb; sC[w] = c; }
    __syncthreads();
    if (w == 0) {
        a = (l < (K3_TPB >> 5)) ? sA[l] : 0.f;
        bb = (l < (K3_TPB >> 5)) ? sB[l] : 0.f;
        c = (l < (K3_TPB >> 5)) ? sC[l] : 0;
        a = warpRedF(a); bb = warpRedF(bb); c = warpRedI(c);
        if (l == 0) {
            if (a != 0.f)  atomicAdd(&g_loss_l, (double)a);
            if (bb != 0.f) atomicAdd(&g_loss_c, (double)bb);
            if (c)         atomicAdd(&g_numpos[blockIdx.y], c);
        }
    }
}

// Hard-negative mining: one block per batch. MSB-first 8-bit radix select
// (4 passes over this batch's 98KB key slice; passes 2-4 hit L1), then the
// sum of selected negatives, all fused.
__global__ void __launch_bounds__(1024) k_mine(int P) {
    const int b = blockIdx.x;
    const int tid = threadIdx.x;
    __shared__ unsigned sh_hist[256];
    __shared__ unsigned sh_suf[256];
    __shared__ unsigned sh_pref, sh_mask, sh_k;
    __shared__ int sh_state;   // 0 normal, 1 take-all, 2 none
    const unsigned* __restrict__ keys = g_key + (size_t)b * P;

    if (tid == 0) {
        long long k = 3LL * (long long)g_numpos[b];
        if (k > P - 1) k = P - 1;
        sh_k = (unsigned)(k > 0 ? k : 0);
        sh_pref = 0u; sh_mask = 0u;
        sh_state = (k <= 0) ? 2 : 0;
    }
    __syncthreads();

    if (sh_state == 0) {
        for (int j = 3; j >= 0; j--) {
            if (tid < 256) sh_hist[tid] = 0u;
            __syncthreads();
            const unsigned mask = sh_mask, pref = sh_pref;
            for (int i = tid; i < P; i += 1024) {
                unsigned key = keys[i];
                if (key && (key & mask) == pref)
                    atomicAdd(&sh_hist[(key >> (8 * j)) & 255u], 1u);
            }
            __syncthreads();
            if (tid < 256) sh_suf[tid] = sh_hist[tid];
            __syncthreads();
            // inclusive suffix scan over 256 bins
            for (int off = 1; off < 256; off <<= 1) {
                unsigned v = 0;
                if (tid < 256 && tid + off < 256) v = sh_suf[tid + off];
                __syncthreads();
                if (tid < 256) sh_suf[tid] += v;
                __syncthreads();
            }
            if (tid == 0 && j == 3 && sh_suf[0] < sh_k) sh_state = 1;
            __syncthreads();
            if (sh_state == 1) break;
            if (tid < 256) {
                unsigned incl  = sh_suf[tid];
                unsigned above = (tid == 255) ? 0u : sh_suf[tid + 1];
                unsigned k = sh_k;
                if (above < k && incl >= k) {
                    sh_pref = pref | ((unsigned)tid << (8 * j));
                    sh_mask = mask | (0xFFu << (8 * j));
                    sh_k = k - above;
                }
            }
            __syncthreads();
        }
    }

    const int st = sh_state;
    const unsigned T = sh_pref;
    float acc = 0.f;
    if (st == 1) {
        for (int i = tid; i < P; i += 1024) {
            unsigned key = keys[i];
            if (key) acc += __uint_as_float(key);
        }
    } else if (st == 0) {
        for (int i = tid; i < P; i += 1024) {
            unsigned key = keys[i];
            if (key > T) acc += __uint_as_float(key);
        }
    }
    acc = warpRedF(acc);
    __shared__ float sA[32];
    int w = tid >> 5, l = tid & 31;
    if (l == 0) sA[w] = acc;
    __syncthreads();
    if (w == 0) {
        acc = sA[l];
        acc = warpRedF(acc);
        if (l == 0) {
            double tot = (double)acc;
            if (st == 0) tot += (double)sh_k * (double)__uint_as_float(T);
            if (tot != 0.0) atomicAdd(&g_loss_c, tot);
        }
    }
}

__global__ void k_final(float* out, int B) {
    int l = threadIdx.x;                       // 32 threads
    int n = 0;
    for (int b = l; b < B; b += 32) n += g_numpos[b];
    n = warpRedI(n);
    if (l == 0) {
        double N = (n > 0) ? (double)n : 1.0;
        out[0] = (float)(g_loss_l / N);
        out[1] = (float)(g_loss_c / N);
    }
}

// ------------------------------ launch -------------------------------------
extern "C" void kernel_launch(void* const* d_in, const int* in_sizes, int n_in,
                              void* d_out, int out_size) {
    const float* loc     = (const float*)d_in[0];
    const float* conf    = (const float*)d_in[1];
    const float* priors  = (const float*)d_in[2];
    const float* tboxes  = (const float*)d_in[3];
    const int*   tlabels = (const int*)d_in[4];

    int P = in_sizes[2] / 4;
    int B = in_sizes[0] / (P * 4);
    if (B > BMAX) B = BMAX;

    k_init<<<8, 256>>>();

    dim3 g1((P + K1_TPB * K1_PPT - 1) / (K1_TPB * K1_PPT), B);
    k_match<<<g1, K1_TPB>>>(priors, tboxes, P);

    k_fixup<<<1, BMAX>>>(P, B);

    int NT = (P + TILE_P - 1) / TILE_P;
    dim3 g3((NT + TILES_PB - 1) / TILES_PB, B);
    k_ce<<<g3, K3_TPB>>>(conf, loc, priors, tboxes, tlabels, P, NT);

    k_mine<<<B, 1024>>>(P);

    k_final<<<1, 32>>>((float*)d_out, B);
}